// round 6
// baseline (speedup 1.0000x reference)
#include <cuda_runtime.h>

// Problem constants (fixed by dataset)
#define DD    128        // feature dim
#define KK2   256        // concat K = 2*D
#define NMAX  50048      // padded
#define BPELE (32 * 4 * 32 * 8)   // 32768 elements per layer of permuted B

// Scratch (device globals: allocations are forbidden)
__device__ float g_h0[NMAX * DD];
__device__ float g_h1[NMAX * DD];
__device__ float g_neigh1[NMAX * DD];
__device__ float g_neigh2[NMAX * DD];
__device__ float g_deg[NMAX];
// Fragment-major pre-split tf32 B:
// idx = (kb*4+wn)*256 + lane*8 + r*4 + nt ; value = Bcat[kb*8 + t + 4r][wn*32 + nt*8 + g]
// where lane = g*4+t, Bcat[k][n] = k<128 ? Ws[n][k] : Wn[n][k-128]
__device__ unsigned g_Bph[2][BPELE];
__device__ unsigned g_Bpl[2][BPELE];

__device__ __forceinline__ unsigned f2tf(float x)
{
    unsigned r;
    asm("cvt.rna.tf32.f32 %0, %1;" : "=r"(r) : "f"(x));
    return r;
}

// ---------------------------------------------------------------------------
__global__ void k_init(const int* __restrict__ node_ids,
                       const float* __restrict__ emb, int N)
{
    int total = N * DD;
    for (int i = blockIdx.x * blockDim.x + threadIdx.x; i < total;
         i += gridDim.x * blockDim.x) {
        int n = i >> 7;
        int k = i & 127;
        g_h0[i]     = emb[(size_t)node_ids[n] * DD + k];
        g_neigh1[i] = 0.0f;
        g_neigh2[i] = 0.0f;
        if (i < N) g_deg[i] = 0.0f;
    }
}

// ---------------------------------------------------------------------------
// Build fragment-major tf32 hi/lo B for both layers
// ---------------------------------------------------------------------------
__global__ void k_transB(const float* __restrict__ Ws1, const float* __restrict__ Wn1,
                         const float* __restrict__ Ws2, const float* __restrict__ Wn2)
{
    int i = blockIdx.x * blockDim.x + threadIdx.x;   // 2 * 32768
    if (i >= 2 * BPELE) return;
    int l   = i >= BPELE;
    int idx = l ? (i - BPELE) : i;
    int nt  = idx & 3;
    int r   = (idx >> 2) & 1;
    int t   = (idx >> 3) & 3;
    int g   = (idx >> 5) & 7;
    int wn  = (idx >> 8) & 3;
    int kb  = idx >> 10;

    int k = kb * 8 + t + 4 * r;
    int n = wn * 32 + nt * 8 + g;
    const float* Ws = l ? Ws2 : Ws1;
    const float* Wn = l ? Wn2 : Wn1;
    float v = (k < DD) ? Ws[n * DD + k] : Wn[n * DD + (k - DD)];
    unsigned hi = f2tf(v);
    unsigned lo = f2tf(v - __uint_as_float(hi));
    g_Bph[l][idx] = hi;
    g_Bpl[l][idx] = lo;
}

// ---------------------------------------------------------------------------
// Scatter: one warp per edge. neigh[dst] += w * h[src] via RED.128
// ---------------------------------------------------------------------------
__global__ void k_scatter(const float* __restrict__ h,
                          const int* __restrict__ src,
                          const int* __restrict__ dst,
                          const float* __restrict__ w,
                          float* __restrict__ neigh,
                          int E, int count_deg)
{
    int gw   = (blockIdx.x * blockDim.x + threadIdx.x) >> 5;
    int lane = threadIdx.x & 31;
    if (gw >= E) return;

    int   s  = src[gw];
    int   t  = dst[gw];
    float we = w[gw];

    if (count_deg && lane == 0) atomicAdd(&g_deg[t], 1.0f);

    float4 v = *reinterpret_cast<const float4*>(h + (size_t)s * DD + lane * 4);
    v.x *= we; v.y *= we; v.z *= we; v.w *= we;
    float* p = neigh + (size_t)t * DD + lane * 4;
#if defined(__CUDA_ARCH__) && __CUDA_ARCH__ >= 900
    atomicAdd(reinterpret_cast<float4*>(p), v);
#else
    atomicAdd(p + 0, v.x); atomicAdd(p + 1, v.y);
    atomicAdd(p + 2, v.z); atomicAdd(p + 3, v.w);
#endif
}

// ---------------------------------------------------------------------------
// Tensor-core GEMM (3xTF32): out[M x 128] = [h | neigh/deg][M x 256] @ Bcat + bias
// 512 threads = 16 warps (4m x 4n), warp tile 32m x 32n, 128x128 block tile.
// BK=16 (2 k8 sub-blocks), A in smem with k-interleave k'=2(k&3)+(k>>2) so a
// fragment k-pair (t, t+4) is one LDS.64. B fragments come straight from the
// fragment-major global arrays via LDG.128 (L1-broadcast across wm warps).
// One __syncthreads per chunk (store-after-compute double buffer).
// ---------------------------------------------------------------------------
#define KKS 1028   // per-kk A slab: 128 rows * 8 k' + 4 pad (bank stagger)

__device__ __forceinline__ void mma8(float* d, const unsigned* a, const unsigned* b)
{
    asm volatile(
        "mma.sync.aligned.m16n8k8.row.col.f32.tf32.tf32.f32 "
        "{%0,%1,%2,%3}, {%4,%5,%6,%7}, {%8,%9}, {%0,%1,%2,%3};"
        : "+f"(d[0]), "+f"(d[1]), "+f"(d[2]), "+f"(d[3])
        : "r"(a[0]), "r"(a[1]), "r"(a[2]), "r"(a[3]), "r"(b[0]), "r"(b[1]));
}

__global__ void __launch_bounds__(512, 1)
k_gemm(const float* __restrict__ hmat, const float* __restrict__ nmat,
       const unsigned* __restrict__ Bph, const unsigned* __restrict__ Bpl,
       const float* __restrict__ bias,
       float* __restrict__ out, int M, int do_relu)
{
    __shared__ unsigned Ah[4 * KKS];   // [buf2][kk2][m128][k'8] (+pad)
    __shared__ unsigned Al[4 * KKS];

    int tid  = threadIdx.x;
    int m0   = blockIdx.x * 128;
    int wid  = tid >> 5;
    int lane = tid & 31;
    int wm   = wid & 3;              // rows wm*32..+31
    int wn   = wid >> 2;             // cols wn*32..+31
    int g    = lane >> 2;
    int t    = lane & 3;

    // ---- A loader state (threads 0..255): row m0 + (tid>>1), kk = tid&1 ----
    int   lm   = tid >> 1;
    int   lkk  = tid & 1;
    bool  lact = (tid < 256);
    int   lrow = m0 + lm;
    float invd = 1.0f;
    if (lact) {
        float d = (lrow < M) ? g_deg[lrow] : 1.0f;
        invd = 1.0f / fmaxf(d, 1.0f);
    }

    float acc[2][4][4];
#pragma unroll
    for (int mt = 0; mt < 2; ++mt)
#pragma unroll
        for (int nt = 0; nt < 4; ++nt)
#pragma unroll
            for (int v = 0; v < 4; ++v) acc[mt][nt][v] = 0.0f;

    // Load chunk c's A slice (8 k of this thread's row/kk) and split hi/lo,
    // packed in k'-interleaved word order.
    uint4 wh0, wh1, wl0, wl1;
    auto ldgA = [&](int c) {
        float4 v0, v1;
        int gk = c * 16 + lkk * 8;
        if (!lact || lrow >= M) {
            v0 = make_float4(0.f, 0.f, 0.f, 0.f);
            v1 = v0;
        } else if (gk < DD) {
            v0 = *reinterpret_cast<const float4*>(hmat + (size_t)lrow * DD + gk);
            v1 = *reinterpret_cast<const float4*>(hmat + (size_t)lrow * DD + gk + 4);
        } else {
            v0 = *reinterpret_cast<const float4*>(nmat + (size_t)lrow * DD + gk - DD);
            v1 = *reinterpret_cast<const float4*>(nmat + (size_t)lrow * DD + gk - DD + 4);
            v0.x *= invd; v0.y *= invd; v0.z *= invd; v0.w *= invd;
            v1.x *= invd; v1.y *= invd; v1.z *= invd; v1.w *= invd;
        }
        // hi/lo split
        unsigned h0x = f2tf(v0.x), h0y = f2tf(v0.y), h0z = f2tf(v0.z), h0w = f2tf(v0.w);
        unsigned h1x = f2tf(v1.x), h1y = f2tf(v1.y), h1z = f2tf(v1.z), h1w = f2tf(v1.w);
        unsigned l0x = f2tf(v0.x - __uint_as_float(h0x));
        unsigned l0y = f2tf(v0.y - __uint_as_float(h0y));
        unsigned l0z = f2tf(v0.z - __uint_as_float(h0z));
        unsigned l0w = f2tf(v0.w - __uint_as_float(h0w));
        unsigned l1x = f2tf(v1.x - __uint_as_float(h1x));
        unsigned l1y = f2tf(v1.y - __uint_as_float(h1y));
        unsigned l1z = f2tf(v1.z - __uint_as_float(h1z));
        unsigned l1w = f2tf(v1.w - __uint_as_float(h1w));
        // k' words: w0 = k{0,4,1,5}, w1 = k{2,6,3,7}
        wh0 = make_uint4(h0x, h1x, h0y, h1y);
        wh1 = make_uint4(h0z, h1z, h0w, h1w);
        wl0 = make_uint4(l0x, l1x, l0y, l1y);
        wl1 = make_uint4(l0z, l1z, l0w, l1w);
    };
    auto stA = [&](int buf) {
        if (!lact) return;
        int base = (buf * 2 + lkk) * KKS + lm * 8;
        *reinterpret_cast<uint4*>(&Ah[base])     = wh0;
        *reinterpret_cast<uint4*>(&Ah[base + 4]) = wh1;
        *reinterpret_cast<uint4*>(&Al[base])     = wl0;
        *reinterpret_cast<uint4*>(&Al[base + 4]) = wl1;
    };

    ldgA(0);
    stA(0);
    __syncthreads();

    const unsigned* BhW = Bph + (size_t)wn * 256 + lane * 8;   // + kb*1024
    const unsigned* BlW = Bpl + (size_t)wn * 256 + lane * 8;

    for (int c = 0; c < 16; ++c) {
        int buf = c & 1;
        if (c < 15) ldgA(c + 1);   // issue global loads early

#pragma unroll
        for (int kk = 0; kk < 2; ++kk) {
            int kb = c * 2 + kk;
            // B fragments (hi/lo), 4x LDG.128
            uint4 bh0 = *reinterpret_cast<const uint4*>(BhW + kb * 1024);
            uint4 bh1 = *reinterpret_cast<const uint4*>(BhW + kb * 1024 + 4);
            uint4 bl0 = *reinterpret_cast<const uint4*>(BlW + kb * 1024);
            uint4 bl1 = *reinterpret_cast<const uint4*>(BlW + kb * 1024 + 4);

            // A fragments via LDS.64
            unsigned ahi[2][4], alo[2][4];
#pragma unroll
            for (int mt = 0; mt < 2; ++mt) {
                int rm   = wm * 32 + mt * 16;
                int baseA = (buf * 2 + kk) * KKS + 2 * t;
                uint2 p0 = *reinterpret_cast<const uint2*>(&Ah[baseA + (rm + g) * 8]);
                uint2 p1 = *reinterpret_cast<const uint2*>(&Ah[baseA + (rm + g + 8) * 8]);
                uint2 q0 = *reinterpret_cast<const uint2*>(&Al[baseA + (rm + g) * 8]);
                uint2 q1 = *reinterpret_cast<const uint2*>(&Al[baseA + (rm + g + 8) * 8]);
                ahi[mt][0] = p0.x; ahi[mt][1] = p1.x; ahi[mt][2] = p0.y; ahi[mt][3] = p1.y;
                alo[mt][0] = q0.x; alo[mt][1] = q1.x; alo[mt][2] = q0.y; alo[mt][3] = q1.y;
            }

            const unsigned* bhp0 = &bh0.x;
            const unsigned* bhp1 = &bh1.x;
            const unsigned* blp0 = &bl0.x;
            const unsigned* blp1 = &bl1.x;
#pragma unroll
            for (int nt = 0; nt < 4; ++nt) {
                unsigned bhi[2] = { bhp0[nt], bhp1[nt] };
                unsigned blo[2] = { blp0[nt], blp1[nt] };
#pragma unroll
                for (int mt = 0; mt < 2; ++mt) {
                    mma8(acc[mt][nt], ahi[mt], bhi);
                    mma8(acc[mt][nt], ahi[mt], blo);
                    mma8(acc[mt][nt], alo[mt], bhi);
                }
            }
        }

        if (c < 15) {
            stA(buf ^ 1);
            __syncthreads();
        }
    }

    // Epilogue: bias (+relu), float2 stores
#pragma unroll
    for (int nt = 0; nt < 4; ++nt) {
        int col = wn * 32 + nt * 8 + 2 * t;
        float bx = bias[col], by = bias[col + 1];
#pragma unroll
        for (int mt = 0; mt < 2; ++mt) {
#pragma unroll
            for (int half = 0; half < 2; ++half) {
                int row = m0 + wm * 32 + mt * 16 + g + 8 * half;
                if (row < M) {
                    float vx = acc[mt][nt][2 * half + 0] + bx;
                    float vy = acc[mt][nt][2 * half + 1] + by;
                    if (do_relu) { vx = fmaxf(vx, 0.f); vy = fmaxf(vy, 0.f); }
                    *reinterpret_cast<float2*>(out + (size_t)row * DD + col)
                        = make_float2(vx, vy);
                }
            }
        }
    }
}

// ---------------------------------------------------------------------------
// init -> transB -> scatter1 -> gemm1 -> scatter2 -> gemm2
// ---------------------------------------------------------------------------
extern "C" void kernel_launch(void* const* d_in, const int* in_sizes, int n_in,
                              void* d_out, int out_size)
{
    const int*   node_ids = (const int*)  d_in[0];
    const int*   esrc     = (const int*)  d_in[1];
    const int*   edst     = (const int*)  d_in[2];
    const float* ew       = (const float*)d_in[3];
    const float* emb      = (const float*)d_in[4];
    const float* Ws1      = (const float*)d_in[5];
    const float* Wn1      = (const float*)d_in[6];
    const float* b1       = (const float*)d_in[7];
    const float* Ws2      = (const float*)d_in[8];
    const float* Wn2      = (const float*)d_in[9];
    const float* b2       = (const float*)d_in[10];

    int N = in_sizes[0];
    int E = in_sizes[1];
    float* out = (float*)d_out;

    void *p_h0_v, *p_h1_v, *p_n1_v, *p_n2_v, *p_Bh_v, *p_Bl_v;
    cudaGetSymbolAddress(&p_h0_v, g_h0);
    cudaGetSymbolAddress(&p_h1_v, g_h1);
    cudaGetSymbolAddress(&p_n1_v, g_neigh1);
    cudaGetSymbolAddress(&p_n2_v, g_neigh2);
    cudaGetSymbolAddress(&p_Bh_v, g_Bph);
    cudaGetSymbolAddress(&p_Bl_v, g_Bpl);
    const float* p_h0 = (const float*)p_h0_v;
    const float* p_h1 = (const float*)p_h1_v;
    const float* p_n1 = (const float*)p_n1_v;
    const float* p_n2 = (const float*)p_n2_v;
    const unsigned* p_Bh = (const unsigned*)p_Bh_v;
    const unsigned* p_Bl = (const unsigned*)p_Bl_v;

    const int TB = 256;
    int sblocks = (E + 7) / 8;
    int gblocks = (N + 127) / 128;

    k_init<<<2048, TB>>>(node_ids, emb, N);
    k_transB<<<(2 * BPELE + TB - 1) / TB, TB>>>(Ws1, Wn1, Ws2, Wn2);

    // Layer 1
    k_scatter<<<sblocks, TB>>>(p_h0, esrc, edst, ew, (float*)p_n1_v, E, 1);
    k_gemm<<<gblocks, 512>>>(p_h0, p_n1, p_Bh, p_Bl, b1, (float*)p_h1_v, N, 1);

    // Layer 2
    k_scatter<<<sblocks, TB>>>(p_h1, esrc, edst, ew, (float*)p_n2_v, E, 0);
    k_gemm<<<gblocks, 512>>>(p_h1, p_n2, p_Bh + BPELE, p_Bl + BPELE,
                             b2, out, N, 0);
}

// round 7
// speedup vs baseline: 1.9124x; 1.9124x over previous
#include <cuda_runtime.h>

// Problem constants (fixed by dataset)
#define DD    128        // feature dim
#define KK2   256        // concat K = 2*D
#define NMAX  50048      // padded
#define BWORDS (KK2 * DD)   // 32768 tf32 words per layer of permuted B

// Scratch (device globals: allocations are forbidden)
__device__ float g_h0[NMAX * DD];
__device__ float g_h1[NMAX * DD];
__device__ float g_neigh1[NMAX * DD];
__device__ float g_neigh2[NMAX * DD];
__device__ float g_deg[NMAX];
// Pre-converted tf32 B, pair-interleaved fragment layout:
// idx = kb8*1024 + n*8 + 2*t + e  ->  Bcat[k][n],  k = kb8*8 + t + 4*e
// (kb8 = 0..31: 8-k block; n = 0..127; t = 0..3; e = 0..1)
// Bcat[k][n] = k<128 ? Ws[n][k] : Wn[n][k-128]
__device__ unsigned g_Bt[2][BWORDS];

__device__ __forceinline__ unsigned f2tf(float x)
{
    unsigned r;
    asm("cvt.rna.tf32.f32 %0, %1;" : "=r"(r) : "f"(x));
    return r;
}

// ---------------------------------------------------------------------------
__global__ void k_init(const int* __restrict__ node_ids,
                       const float* __restrict__ emb, int N)
{
    int total = N * DD;
    for (int i = blockIdx.x * blockDim.x + threadIdx.x; i < total;
         i += gridDim.x * blockDim.x) {
        int n = i >> 7;
        int k = i & 127;
        g_h0[i]     = emb[(size_t)node_ids[n] * DD + k];
        g_neigh1[i] = 0.0f;
        g_neigh2[i] = 0.0f;
        if (i < N) g_deg[i] = 0.0f;
    }
}

// ---------------------------------------------------------------------------
// Build pair-interleaved tf32 B for both layers
// ---------------------------------------------------------------------------
__global__ void k_transB(const float* __restrict__ Ws1, const float* __restrict__ Wn1,
                         const float* __restrict__ Ws2, const float* __restrict__ Wn2)
{
    int i = blockIdx.x * blockDim.x + threadIdx.x;   // 2 * 32768
    if (i >= 2 * BWORDS) return;
    int l   = i >= BWORDS;
    int idx = l ? (i - BWORDS) : i;
    int e   = idx & 1;
    int t   = (idx >> 1) & 3;
    int n   = (idx >> 3) & 127;
    int kb8 = idx >> 10;

    int k = kb8 * 8 + t + 4 * e;
    const float* Ws = l ? Ws2 : Ws1;
    const float* Wn = l ? Wn2 : Wn1;
    float v = (k < DD) ? Ws[n * DD + k] : Wn[n * DD + (k - DD)];
    g_Bt[l][idx] = f2tf(v);
}

// ---------------------------------------------------------------------------
// Scatter: one warp per edge. neigh[dst] += w * h[src] via RED.128
// ---------------------------------------------------------------------------
__global__ void k_scatter(const float* __restrict__ h,
                          const int* __restrict__ src,
                          const int* __restrict__ dst,
                          const float* __restrict__ w,
                          float* __restrict__ neigh,
                          int E, int count_deg)
{
    int gw   = (blockIdx.x * blockDim.x + threadIdx.x) >> 5;
    int lane = threadIdx.x & 31;
    if (gw >= E) return;

    int   s  = src[gw];
    int   t  = dst[gw];
    float we = w[gw];

    if (count_deg && lane == 0) atomicAdd(&g_deg[t], 1.0f);

    float4 v = *reinterpret_cast<const float4*>(h + (size_t)s * DD + lane * 4);
    v.x *= we; v.y *= we; v.z *= we; v.w *= we;
    float* p = neigh + (size_t)t * DD + lane * 4;
#if defined(__CUDA_ARCH__) && __CUDA_ARCH__ >= 900
    atomicAdd(reinterpret_cast<float4*>(p), v);
#else
    atomicAdd(p + 0, v.x); atomicAdd(p + 1, v.y);
    atomicAdd(p + 2, v.z); atomicAdd(p + 3, v.w);
#endif
}

// ---------------------------------------------------------------------------
// Tensor-core GEMM (single-pass TF32, rna-converted operands):
//   out[M x 128] = [h | neigh/deg][M x 256] @ Bcat + bias
// 256 threads = 8 warps (4m x 2n), warp tile 32m x 64n, block tile 128x128.
// BK=16, double-buffered smem (A + B pair-interleaved), 1 sync per chunk.
// B arrives via cp.async straight from the pre-converted global layout.
// All fragment loads are LDS.64 at the 2-phase conflict floor.
// ---------------------------------------------------------------------------
__device__ __forceinline__ void mma8(float* d, const unsigned* a, const unsigned* b)
{
    asm volatile(
        "mma.sync.aligned.m16n8k8.row.col.f32.tf32.tf32.f32 "
        "{%0,%1,%2,%3}, {%4,%5,%6,%7}, {%8,%9}, {%0,%1,%2,%3};"
        : "+f"(d[0]), "+f"(d[1]), "+f"(d[2]), "+f"(d[3])
        : "r"(a[0]), "r"(a[1]), "r"(a[2]), "r"(a[3]), "r"(b[0]), "r"(b[1]));
}

__device__ __forceinline__ void cpasync16(unsigned saddr, const void* gptr)
{
    asm volatile("cp.async.ca.shared.global [%0], [%1], 16;"
                 :: "r"(saddr), "l"(gptr));
}

__global__ void __launch_bounds__(256, 2)
k_gemm(const float* __restrict__ hmat, const float* __restrict__ nmat,
       const unsigned* __restrict__ Bt, const float* __restrict__ bias,
       float* __restrict__ out, int M, int do_relu)
{
    // per buffer: 2 kk-slabs of [128 rows][8 words] = 2048 words (8KB)
    __shared__ unsigned As[2][2048];
    __shared__ unsigned Bs[2][2048];

    int tid  = threadIdx.x;
    int m0   = blockIdx.x * 128;
    int wid  = tid >> 5;
    int lane = tid & 31;
    int wm   = wid & 3;              // rows wm*32..+31
    int wn   = wid >> 2;             // cols wn*64..+63
    int g    = lane >> 2;
    int t    = lane & 3;

    unsigned sB0 = (unsigned)__cvta_generic_to_shared(&Bs[0][0]);

    // A loader: row lm, kk-slab lkk; 8 k per chunk (2 float4)
    int   lm   = tid >> 1;
    int   lkk  = tid & 1;
    int   lrow = m0 + lm;
    float dgg  = (lrow < M) ? g_deg[lrow] : 1.0f;
    float invd = 1.0f / fmaxf(dgg, 1.0f);

    float acc[2][8][4];
#pragma unroll
    for (int mt = 0; mt < 2; ++mt)
#pragma unroll
        for (int nt = 0; nt < 8; ++nt)
#pragma unroll
            for (int v = 0; v < 4; ++v) acc[mt][nt][v] = 0.0f;

    uint4 aw0, aw1;   // pair-interleaved: (k0,k4,k1,k5), (k2,k6,k3,k7)
    auto ldgA = [&](int c) {
        int gk = c * 16 + lkk * 8;
        float4 v0, v1;
        if (lrow >= M) {
            v0 = make_float4(0.f, 0.f, 0.f, 0.f); v1 = v0;
        } else if (gk < DD) {
            v0 = *reinterpret_cast<const float4*>(hmat + (size_t)lrow * DD + gk);
            v1 = *reinterpret_cast<const float4*>(hmat + (size_t)lrow * DD + gk + 4);
        } else {
            v0 = *reinterpret_cast<const float4*>(nmat + (size_t)lrow * DD + gk - DD);
            v1 = *reinterpret_cast<const float4*>(nmat + (size_t)lrow * DD + gk - DD + 4);
            v0.x *= invd; v0.y *= invd; v0.z *= invd; v0.w *= invd;
            v1.x *= invd; v1.y *= invd; v1.z *= invd; v1.w *= invd;
        }
        aw0 = make_uint4(f2tf(v0.x), f2tf(v1.x), f2tf(v0.y), f2tf(v1.y));
        aw1 = make_uint4(f2tf(v0.z), f2tf(v1.z), f2tf(v0.w), f2tf(v1.w));
    };
    auto stA = [&](int buf) {
        unsigned* p = &As[buf][lkk * 1024 + lm * 8];
        *reinterpret_cast<uint4*>(p)     = aw0;
        *reinterpret_cast<uint4*>(p + 4) = aw1;
    };
    auto cpB = [&](int c, int buf) {
        const unsigned* gsrc = Bt + c * 2048 + tid * 8;
        unsigned sa = sB0 + (buf * 2048 + tid * 8) * 4;
        cpasync16(sa, gsrc);
        cpasync16(sa + 16, gsrc + 4);
        asm volatile("cp.async.commit_group;" ::: "memory");
    };

    // Prologue: chunk 0
    cpB(0, 0);
    ldgA(0);
    stA(0);
    asm volatile("cp.async.wait_group 0;" ::: "memory");
    __syncthreads();

    for (int c = 0; c < 16; ++c) {
        int buf = c & 1;
        if (c < 15) {
            cpB(c + 1, buf ^ 1);   // async into the other buffer
            ldgA(c + 1);           // register-staged (needs cvt)
        }

#pragma unroll
        for (int kk = 0; kk < 2; ++kk) {
            const unsigned* Ap = &As[buf][kk * 1024];
            const unsigned* Bp = &Bs[buf][kk * 1024];

            unsigned a[2][4];
#pragma unroll
            for (int mt = 0; mt < 2; ++mt) {
                int rm = wm * 32 + mt * 16;
                uint2 p0 = *reinterpret_cast<const uint2*>(&Ap[(rm + g) * 8 + 2 * t]);
                uint2 p1 = *reinterpret_cast<const uint2*>(&Ap[(rm + g + 8) * 8 + 2 * t]);
                a[mt][0] = p0.x; a[mt][1] = p1.x; a[mt][2] = p0.y; a[mt][3] = p1.y;
            }
#pragma unroll
            for (int nt = 0; nt < 8; ++nt) {
                int n = wn * 64 + nt * 8 + g;
                uint2 bb = *reinterpret_cast<const uint2*>(&Bp[n * 8 + 2 * t]);
                unsigned b[2] = { bb.x, bb.y };
                mma8(acc[0][nt], a[0], b);
                mma8(acc[1][nt], a[1], b);
            }
        }

        if (c < 15) {
            stA(buf ^ 1);
            asm volatile("cp.async.wait_group 0;" ::: "memory");
            __syncthreads();
        }
    }

    // Epilogue: bias (+relu), float2 stores
#pragma unroll
    for (int nt = 0; nt < 8; ++nt) {
        int col = wn * 64 + nt * 8 + 2 * t;
        float bx = bias[col], by = bias[col + 1];
#pragma unroll
        for (int mt = 0; mt < 2; ++mt) {
#pragma unroll
            for (int half = 0; half < 2; ++half) {
                int row = m0 + wm * 32 + mt * 16 + g + 8 * half;
                if (row < M) {
                    float vx = acc[mt][nt][2 * half + 0] + bx;
                    float vy = acc[mt][nt][2 * half + 1] + by;
                    if (do_relu) { vx = fmaxf(vx, 0.f); vy = fmaxf(vy, 0.f); }
                    *reinterpret_cast<float2*>(out + (size_t)row * DD + col)
                        = make_float2(vx, vy);
                }
            }
        }
    }
}

// ---------------------------------------------------------------------------
// init -> transB -> scatter1 -> gemm1 -> scatter2 -> gemm2
// ---------------------------------------------------------------------------
extern "C" void kernel_launch(void* const* d_in, const int* in_sizes, int n_in,
                              void* d_out, int out_size)
{
    const int*   node_ids = (const int*)  d_in[0];
    const int*   esrc     = (const int*)  d_in[1];
    const int*   edst     = (const int*)  d_in[2];
    const float* ew       = (const float*)d_in[3];
    const float* emb      = (const float*)d_in[4];
    const float* Ws1      = (const float*)d_in[5];
    const float* Wn1      = (const float*)d_in[6];
    const float* b1       = (const float*)d_in[7];
    const float* Ws2      = (const float*)d_in[8];
    const float* Wn2      = (const float*)d_in[9];
    const float* b2       = (const float*)d_in[10];

    int N = in_sizes[0];
    int E = in_sizes[1];
    float* out = (float*)d_out;

    void *p_h0_v, *p_h1_v, *p_n1_v, *p_n2_v, *p_Bt_v;
    cudaGetSymbolAddress(&p_h0_v, g_h0);
    cudaGetSymbolAddress(&p_h1_v, g_h1);
    cudaGetSymbolAddress(&p_n1_v, g_neigh1);
    cudaGetSymbolAddress(&p_n2_v, g_neigh2);
    cudaGetSymbolAddress(&p_Bt_v, g_Bt);
    const float* p_h0 = (const float*)p_h0_v;
    const float* p_h1 = (const float*)p_h1_v;
    const float* p_n1 = (const float*)p_n1_v;
    const float* p_n2 = (const float*)p_n2_v;
    const unsigned* p_Bt = (const unsigned*)p_Bt_v;

    const int TB = 256;
    int sblocks = (E + 7) / 8;
    int gblocks = (N + 127) / 128;

    k_init<<<2048, TB>>>(node_ids, emb, N);
    k_transB<<<(2 * BWORDS + TB - 1) / TB, TB>>>(Ws1, Wn1, Ws2, Wn2);

    // Layer 1
    k_scatter<<<sblocks, TB>>>(p_h0, esrc, edst, ew, (float*)p_n1_v, E, 1);
    k_gemm<<<gblocks, TB>>>(p_h0, p_n1, p_Bt, b1, (float*)p_h1_v, N, 1);

    // Layer 2
    k_scatter<<<sblocks, TB>>>(p_h1, esrc, edst, ew, (float*)p_n2_v, E, 0);
    k_gemm<<<gblocks, TB>>>(p_h1, p_n2, p_Bt + BWORDS, b2, out, N, 0);
}

// round 8
// speedup vs baseline: 2.6173x; 1.3686x over previous
#include <cuda_runtime.h>

// Problem constants (fixed by dataset)
#define DD    128          // feature dim
#define KK2   256          // concat K = 2*D
#define NMAX  50176        // padded to 512*98
#define EMAX  600064
#define BWORDS (KK2 * DD)  // 32768 tf32 words per layer of permuted B
#define SCANB 512
#define NBLK  (NMAX / SCANB)   // 98

// Scratch (device globals: allocations are forbidden)
__device__ float g_h0[NMAX * DD];
__device__ float g_h1[NMAX * DD];
__device__ float g_nb[NMAX * DD];    // neigh / max(deg,1) (gather output)
__device__ int   g_cnt[NMAX];        // in-degree (CSR row length)
__device__ int   g_off[NMAX];        // CSR row offsets (exclusive scan)
__device__ int   g_cur[NMAX];        // fill cursors
__device__ int   g_bsum[NBLK];       // scan partials
__device__ int2  g_ep[EMAX];         // packed (src, weight-bits), dst-sorted
// Pre-converted tf32 B, pair-interleaved fragment layout:
// idx = kb8*1024 + n*8 + 2*t + e -> Bcat[k][n], k = kb8*8 + t + 4*e
// Bcat[k][n] = k<128 ? Ws[n][k] : Wn[n][k-128]
__device__ unsigned g_Bt[2][BWORDS];

__device__ __forceinline__ unsigned f2tf(float x)
{
    unsigned r;
    asm("cvt.rna.tf32.f32 %0, %1;" : "=r"(r) : "f"(x));
    return r;
}

// ---------------------------------------------------------------------------
// h0 = emb[node_ids]; zero CSR counters/cursors
// ---------------------------------------------------------------------------
__global__ void k_init(const int* __restrict__ node_ids,
                       const float* __restrict__ emb, int N)
{
    int total = N * DD;
    for (int i = blockIdx.x * blockDim.x + threadIdx.x; i < total;
         i += gridDim.x * blockDim.x) {
        int n = i >> 7;
        int k = i & 127;
        g_h0[i] = emb[(size_t)node_ids[n] * DD + k];
        if (i < NMAX) { g_cnt[i] = 0; g_cur[i] = 0; }
    }
}

// ---------------------------------------------------------------------------
// CSR build: histogram -> 3-step exclusive scan -> fill
// ---------------------------------------------------------------------------
__global__ void k_hist(const int* __restrict__ dst, int E)
{
    int i = blockIdx.x * blockDim.x + threadIdx.x;
    if (i < E) atomicAdd(&g_cnt[dst[i]], 1);
}

__global__ void k_scan1()   // per-block sums of cnt
{
    __shared__ int s[SCANB];
    int i = blockIdx.x * SCANB + threadIdx.x;
    s[threadIdx.x] = g_cnt[i];
    __syncthreads();
    for (int d = SCANB / 2; d > 0; d >>= 1) {
        if (threadIdx.x < d) s[threadIdx.x] += s[threadIdx.x + d];
        __syncthreads();
    }
    if (threadIdx.x == 0) g_bsum[blockIdx.x] = s[0];
}

__global__ void k_scan2()   // exclusive scan of the NBLK partials (1 thread)
{
    int run = 0;
    for (int b = 0; b < NBLK; ++b) {
        int t = g_bsum[b];
        g_bsum[b] = run;
        run += t;
    }
}

__global__ void k_scan3()   // per-block exclusive scan + base
{
    __shared__ int s[SCANB];
    int i   = blockIdx.x * SCANB + threadIdx.x;
    int own = g_cnt[i];
    s[threadIdx.x] = own;
    __syncthreads();
    // Hillis-Steele inclusive scan
    for (int d = 1; d < SCANB; d <<= 1) {
        int v = (threadIdx.x >= d) ? s[threadIdx.x - d] : 0;
        __syncthreads();
        s[threadIdx.x] += v;
        __syncthreads();
    }
    g_off[i] = g_bsum[blockIdx.x] + s[threadIdx.x] - own;
}

__global__ void k_fill(const int* __restrict__ src,
                       const int* __restrict__ dst,
                       const float* __restrict__ w, int E)
{
    int i = blockIdx.x * blockDim.x + threadIdx.x;
    if (i >= E) return;
    int d = dst[i];
    int p = atomicAdd(&g_cur[d], 1);
    g_ep[g_off[d] + p] = make_int2(src[i], __float_as_int(w[i]));
}

// ---------------------------------------------------------------------------
// Gather: one warp per dst node. nb[n] = (sum_e w_e * h[src_e]) / max(len,1)
// Unroll x2 for MLP=2 on the 512B h-row gathers.
// ---------------------------------------------------------------------------
__global__ void k_gather(const float* __restrict__ h, float* __restrict__ nb,
                         int N)
{
    int gw   = (blockIdx.x * blockDim.x + threadIdx.x) >> 5;
    int lane = threadIdx.x & 31;
    if (gw >= N) return;

    int off = g_off[gw];
    int len = g_cnt[gw];

    float4 acc = make_float4(0.f, 0.f, 0.f, 0.f);
    int j = 0;
    for (; j + 1 < len; j += 2) {
        int2 e0 = g_ep[off + j];
        int2 e1 = g_ep[off + j + 1];
        float4 v0 = *reinterpret_cast<const float4*>(h + (size_t)e0.x * DD + lane * 4);
        float4 v1 = *reinterpret_cast<const float4*>(h + (size_t)e1.x * DD + lane * 4);
        float w0 = __int_as_float(e0.y);
        float w1 = __int_as_float(e1.y);
        acc.x += w0 * v0.x + w1 * v1.x;
        acc.y += w0 * v0.y + w1 * v1.y;
        acc.z += w0 * v0.z + w1 * v1.z;
        acc.w += w0 * v0.w + w1 * v1.w;
    }
    if (j < len) {
        int2 e0 = g_ep[off + j];
        float4 v0 = *reinterpret_cast<const float4*>(h + (size_t)e0.x * DD + lane * 4);
        float w0 = __int_as_float(e0.y);
        acc.x += w0 * v0.x; acc.y += w0 * v0.y;
        acc.z += w0 * v0.z; acc.w += w0 * v0.w;
    }

    float inv = 1.0f / (float)max(len, 1);
    acc.x *= inv; acc.y *= inv; acc.z *= inv; acc.w *= inv;
    *reinterpret_cast<float4*>(nb + (size_t)gw * DD + lane * 4) = acc;
}

// ---------------------------------------------------------------------------
// Build pair-interleaved tf32 B for both layers
// ---------------------------------------------------------------------------
__global__ void k_transB(const float* __restrict__ Ws1, const float* __restrict__ Wn1,
                         const float* __restrict__ Ws2, const float* __restrict__ Wn2)
{
    int i = blockIdx.x * blockDim.x + threadIdx.x;   // 2 * 32768
    if (i >= 2 * BWORDS) return;
    int l   = i >= BWORDS;
    int idx = l ? (i - BWORDS) : i;
    int e   = idx & 1;
    int t   = (idx >> 1) & 3;
    int n   = (idx >> 3) & 127;
    int kb8 = idx >> 10;

    int k = kb8 * 8 + t + 4 * e;
    const float* Ws = l ? Ws2 : Ws1;
    const float* Wn = l ? Wn2 : Wn1;
    float v = (k < DD) ? Ws[n * DD + k] : Wn[n * DD + (k - DD)];
    g_Bt[l][idx] = f2tf(v);
}

// ---------------------------------------------------------------------------
// Tensor-core GEMM (single-pass TF32):
//   out[M x 128] = [h | nb][M x 256] @ Bcat + bias
// 256 threads = 8 warps (4m x 2n), warp tile 32m x 64n, block tile 128x128.
// BK=16, double-buffered smem, 1 sync per chunk; B staged via cp.async.
// ---------------------------------------------------------------------------
__device__ __forceinline__ void mma8(float* d, const unsigned* a, const unsigned* b)
{
    asm volatile(
        "mma.sync.aligned.m16n8k8.row.col.f32.tf32.tf32.f32 "
        "{%0,%1,%2,%3}, {%4,%5,%6,%7}, {%8,%9}, {%0,%1,%2,%3};"
        : "+f"(d[0]), "+f"(d[1]), "+f"(d[2]), "+f"(d[3])
        : "r"(a[0]), "r"(a[1]), "r"(a[2]), "r"(a[3]), "r"(b[0]), "r"(b[1]));
}

__device__ __forceinline__ void cpasync16(unsigned saddr, const void* gptr)
{
    asm volatile("cp.async.ca.shared.global [%0], [%1], 16;"
                 :: "r"(saddr), "l"(gptr));
}

__global__ void __launch_bounds__(256, 2)
k_gemm(const float* __restrict__ hmat, const float* __restrict__ nmat,
       const unsigned* __restrict__ Bt, const float* __restrict__ bias,
       float* __restrict__ out, int M, int do_relu)
{
    __shared__ unsigned As[2][2048];
    __shared__ unsigned Bs[2][2048];

    int tid  = threadIdx.x;
    int m0   = blockIdx.x * 128;
    int wid  = tid >> 5;
    int lane = tid & 31;
    int wm   = wid & 3;
    int wn   = wid >> 2;
    int g    = lane >> 2;
    int t    = lane & 3;

    unsigned sB0 = (unsigned)__cvta_generic_to_shared(&Bs[0][0]);

    int lm   = tid >> 1;
    int lkk  = tid & 1;
    int lrow = m0 + lm;

    float acc[2][8][4];
#pragma unroll
    for (int mt = 0; mt < 2; ++mt)
#pragma unroll
        for (int nt = 0; nt < 8; ++nt)
#pragma unroll
            for (int v = 0; v < 4; ++v) acc[mt][nt][v] = 0.0f;

    uint4 aw0, aw1;
    auto ldgA = [&](int c) {
        int gk = c * 16 + lkk * 8;
        float4 v0, v1;
        if (lrow >= M) {
            v0 = make_float4(0.f, 0.f, 0.f, 0.f); v1 = v0;
        } else {
            const float* src = (gk < DD) ? (hmat + (size_t)lrow * DD + gk)
                                         : (nmat + (size_t)lrow * DD + gk - DD);
            v0 = *reinterpret_cast<const float4*>(src);
            v1 = *reinterpret_cast<const float4*>(src + 4);
        }
        aw0 = make_uint4(f2tf(v0.x), f2tf(v1.x), f2tf(v0.y), f2tf(v1.y));
        aw1 = make_uint4(f2tf(v0.z), f2tf(v1.z), f2tf(v0.w), f2tf(v1.w));
    };
    auto stA = [&](int buf) {
        unsigned* p = &As[buf][lkk * 1024 + lm * 8];
        *reinterpret_cast<uint4*>(p)     = aw0;
        *reinterpret_cast<uint4*>(p + 4) = aw1;
    };
    auto cpB = [&](int c, int buf) {
        const unsigned* gsrc = Bt + c * 2048 + tid * 8;
        unsigned sa = sB0 + (buf * 2048 + tid * 8) * 4;
        cpasync16(sa, gsrc);
        cpasync16(sa + 16, gsrc + 4);
        asm volatile("cp.async.commit_group;" ::: "memory");
    };

    cpB(0, 0);
    ldgA(0);
    stA(0);
    asm volatile("cp.async.wait_group 0;" ::: "memory");
    __syncthreads();

    for (int c = 0; c < 16; ++c) {
        int buf = c & 1;
        if (c < 15) {
            cpB(c + 1, buf ^ 1);
            ldgA(c + 1);
        }

#pragma unroll
        for (int kk = 0; kk < 2; ++kk) {
            const unsigned* Ap = &As[buf][kk * 1024];
            const unsigned* Bp = &Bs[buf][kk * 1024];

            unsigned a[2][4];
#pragma unroll
            for (int mt = 0; mt < 2; ++mt) {
                int rm = wm * 32 + mt * 16;
                uint2 p0 = *reinterpret_cast<const uint2*>(&Ap[(rm + g) * 8 + 2 * t]);
                uint2 p1 = *reinterpret_cast<const uint2*>(&Ap[(rm + g + 8) * 8 + 2 * t]);
                a[mt][0] = p0.x; a[mt][1] = p1.x; a[mt][2] = p0.y; a[mt][3] = p1.y;
            }
#pragma unroll
            for (int nt = 0; nt < 8; ++nt) {
                int n = wn * 64 + nt * 8 + g;
                uint2 bb = *reinterpret_cast<const uint2*>(&Bp[n * 8 + 2 * t]);
                unsigned b[2] = { bb.x, bb.y };
                mma8(acc[0][nt], a[0], b);
                mma8(acc[1][nt], a[1], b);
            }
        }

        if (c < 15) {
            stA(buf ^ 1);
            asm volatile("cp.async.wait_group 0;" ::: "memory");
            __syncthreads();
        }
    }

#pragma unroll
    for (int nt = 0; nt < 8; ++nt) {
        int col = wn * 64 + nt * 8 + 2 * t;
        float bx = bias[col], by = bias[col + 1];
#pragma unroll
        for (int mt = 0; mt < 2; ++mt) {
#pragma unroll
            for (int half = 0; half < 2; ++half) {
                int row = m0 + wm * 32 + mt * 16 + g + 8 * half;
                if (row < M) {
                    float vx = acc[mt][nt][2 * half + 0] + bx;
                    float vy = acc[mt][nt][2 * half + 1] + by;
                    if (do_relu) { vx = fmaxf(vx, 0.f); vy = fmaxf(vy, 0.f); }
                    *reinterpret_cast<float2*>(out + (size_t)row * DD + col)
                        = make_float2(vx, vy);
                }
            }
        }
    }
}

// ---------------------------------------------------------------------------
// init/transB -> CSR build -> [gather -> gemm] x 2
// ---------------------------------------------------------------------------
extern "C" void kernel_launch(void* const* d_in, const int* in_sizes, int n_in,
                              void* d_out, int out_size)
{
    const int*   node_ids = (const int*)  d_in[0];
    const int*   esrc     = (const int*)  d_in[1];
    const int*   edst     = (const int*)  d_in[2];
    const float* ew       = (const float*)d_in[3];
    const float* emb      = (const float*)d_in[4];
    const float* Ws1      = (const float*)d_in[5];
    const float* Wn1      = (const float*)d_in[6];
    const float* b1       = (const float*)d_in[7];
    const float* Ws2      = (const float*)d_in[8];
    const float* Wn2      = (const float*)d_in[9];
    const float* b2       = (const float*)d_in[10];

    int N = in_sizes[0];
    int E = in_sizes[1];
    float* out = (float*)d_out;

    void *p_h0_v, *p_h1_v, *p_nb_v, *p_Bt_v;
    cudaGetSymbolAddress(&p_h0_v, g_h0);
    cudaGetSymbolAddress(&p_h1_v, g_h1);
    cudaGetSymbolAddress(&p_nb_v, g_nb);
    cudaGetSymbolAddress(&p_Bt_v, g_Bt);
    const float* p_h0 = (const float*)p_h0_v;
    const float* p_h1 = (const float*)p_h1_v;
    const float* p_nb = (const float*)p_nb_v;
    const unsigned* p_Bt = (const unsigned*)p_Bt_v;

    const int TB = 256;
    int gblocks  = (N + 127) / 128;
    int eblocks  = (E + TB - 1) / TB;
    int wblocks  = (N * 32 + TB - 1) / TB;   // warp-per-node kernels

    k_init<<<2048, TB>>>(node_ids, emb, N);
    k_transB<<<(2 * BWORDS + TB - 1) / TB, TB>>>(Ws1, Wn1, Ws2, Wn2);

    // CSR build (edges sorted by dst)
    k_hist<<<eblocks, TB>>>(edst, E);
    k_scan1<<<NBLK, SCANB>>>();
    k_scan2<<<1, 1>>>();
    k_scan3<<<NBLK, SCANB>>>();
    k_fill<<<eblocks, TB>>>(esrc, edst, ew, E);

    // Layer 1
    k_gather<<<wblocks, TB>>>(p_h0, (float*)p_nb_v, N);
    k_gemm<<<gblocks, TB>>>(p_h0, p_nb, p_Bt, b1, (float*)p_h1_v, N, 1);

    // Layer 2
    k_gather<<<wblocks, TB>>>(p_h1, (float*)p_nb_v, N);
    k_gemm<<<gblocks, TB>>>(p_h1, p_nb, p_Bt + BWORDS, b2, out, N, 0);
}